// round 6
// baseline (speedup 1.0000x reference)
#include <cuda_runtime.h>
#include <cstdint>
#include <math.h>

#define T_TOK   2048
#define DIM     1024
#define NEXP    8
#define HID     4096
#define TOPK    2
#define MAXROWS (T_TOK * TOPK)   // 4096

// ---------------- scratch (__device__ globals) -------------------------------
__device__ float g_H[(size_t)MAXROWS * HID];        // 64 MB hidden acts (tf32)
__device__ float g_U[(size_t)T_TOK * DIM];          // 8 MB tf32-rounded inputs
__device__ float g_O[(size_t)MAXROWS * DIM];        // 16 MB expert outputs
__device__ float g_W1t[(size_t)NEXP * HID * DIM];   // 134 MB W1^T (tf32) [e][n][k]
__device__ float g_W2t[(size_t)NEXP * DIM * HID];   // 134 MB W2^T (tf32) [e][n][k]
__device__ int   g_rowmap[MAXROWS];                 // slot -> token
__device__ int   g_counts[NEXP];
__device__ int   g_offsets[NEXP + 1];
__device__ int   g_tok_e[T_TOK * TOPK];
__device__ float g_tok_w[T_TOK * TOPK];
__device__ int   g_tok_slot[T_TOK * TOPK];
__device__ float g_dummy[1];

// ---------------- helpers ----------------------------------------------------
__device__ __forceinline__ uint32_t smem_u32(const void* p) {
    uint32_t a;
    asm("{ .reg .u64 t; cvta.to.shared.u64 t, %1; cvt.u32.u64 %0, t; }"
        : "=r"(a) : "l"(p));
    return a;
}
__device__ __forceinline__ float tf32r(float x) {
    float r;
    asm("cvt.rna.tf32.f32 %0, %1;" : "=f"(r) : "f"(x));
    return r;
}

#define CP16(dst, src) \
    asm volatile("cp.async.cg.shared.global [%0], [%1], 16;" :: "r"(dst), "l"(src))
#define CP_COMMIT()  asm volatile("cp.async.commit_group;" ::: "memory")
#define CP_WAIT1()   asm volatile("cp.async.wait_group 1;" ::: "memory")
#define CP_WAITALL() asm volatile("cp.async.wait_all;" ::: "memory")

#define LDSM_X4(r, addr) \
    asm volatile("ldmatrix.sync.aligned.m8n8.x4.shared.b16 {%0,%1,%2,%3}, [%4];" \
        : "=r"((r)[0]), "=r"((r)[1]), "=r"((r)[2]), "=r"((r)[3]) : "r"(addr))

#define MMA_TF32(d, a, b) \
    asm volatile("mma.sync.aligned.m16n8k8.row.col.f32.tf32.tf32.f32 " \
        "{%0,%1,%2,%3}, {%4,%5,%6,%7}, {%8,%9}, {%0,%1,%2,%3};" \
        : "+f"((d)[0]), "+f"((d)[1]), "+f"((d)[2]), "+f"((d)[3]) \
        : "r"((a)[0]), "r"((a)[1]), "r"((a)[2]), "r"((a)[3]), \
          "r"((b)[0]), "r"((b)[1]))

// ---------------- K0: round u -> g_U, reset counters -------------------------
__global__ void k_prep(const float* __restrict__ u)
{
    size_t i = ((size_t)blockIdx.x * blockDim.x + threadIdx.x) * 4;
    if (i < (size_t)T_TOK * DIM) {
        float4 v = *(const float4*)(u + i);
        v.x = tf32r(v.x); v.y = tf32r(v.y); v.z = tf32r(v.z); v.w = tf32r(v.w);
        *(float4*)(g_U + i) = v;
    }
    if (blockIdx.x == 0 && threadIdx.x < NEXP) g_counts[threadIdx.x] = 0;
}

// ---------------- K1: router -------------------------------------------------
__global__ void k_router(const float* __restrict__ u,
                         const float* __restrict__ cent,
                         const float* __restrict__ bias)
{
    int t    = blockIdx.x;
    int warp = threadIdx.x >> 5;
    int lane = threadIdx.x & 31;

    const float* ur = u + (size_t)t * DIM;
    const float* cr = cent + (size_t)warp * DIM;

    float s = 0.f;
    #pragma unroll 8
    for (int i = lane; i < DIM; i += 32) s += ur[i] * cr[i];
    #pragma unroll
    for (int o = 16; o; o >>= 1) s += __shfl_xor_sync(0xffffffffu, s, o);

    __shared__ float sc[NEXP];
    if (lane == 0) sc[warp] = s + bias[warp];
    __syncthreads();

    if (threadIdx.x == 0) {
        float m = sc[0];
        #pragma unroll
        for (int e = 1; e < NEXP; e++) m = fmaxf(m, sc[e]);
        float p[NEXP];
        float den = 0.f;
        #pragma unroll
        for (int e = 0; e < NEXP; e++) { p[e] = __expf(sc[e] - m); den += p[e]; }

        int e0 = 0;
        #pragma unroll
        for (int e = 1; e < NEXP; e++) if (p[e] > p[e0]) e0 = e;
        int e1 = (e0 == 0) ? 1 : 0;
        #pragma unroll
        for (int e = 0; e < NEXP; e++) if (e != e0 && p[e] > p[e1]) e1 = e;

        float inv = 1.f / den;
        g_tok_e[t * 2 + 0] = e0;  g_tok_w[t * 2 + 0] = p[e0] * inv;
        g_tok_e[t * 2 + 1] = e1;  g_tok_w[t * 2 + 1] = p[e1] * inv;
        atomicAdd(&g_counts[e0], 1);
        atomicAdd(&g_counts[e1], 1);
    }
}

// ---------------- K2: fused offsets + maxvio + scatter (single block) --------
__global__ void k_offscatter(float* __restrict__ maxvio_out)
{
    __shared__ int s_off[NEXP];
    __shared__ int s_cur[NEXP];
    int tid = threadIdx.x;
    if (tid < NEXP) s_cur[tid] = 0;
    if (tid == 0) {
        int off = 0, mx = 0;
        #pragma unroll
        for (int e = 0; e < NEXP; e++) {
            s_off[e] = off;
            g_offsets[e] = off;
            int c = g_counts[e];
            off += c;
            if (c > mx) mx = c;
        }
        g_offsets[NEXP] = off;
        const float perfect = (float)(TOPK * T_TOK) / (float)NEXP;
        *maxvio_out = ((float)mx - perfect) / perfect;
    }
    __syncthreads();
    for (int t = tid; t < T_TOK; t += blockDim.x) {
        #pragma unroll
        for (int k = 0; k < TOPK; k++) {
            int e = g_tok_e[t * 2 + k];
            int slot = s_off[e] + atomicAdd(&s_cur[e], 1);
            g_rowmap[slot] = t;
            g_tok_slot[t * 2 + k] = slot;
        }
    }
}

// ---------------- K3: tiled transpose + tf32 round: [e][K][N] -> [e][N][K] ---
__global__ __launch_bounds__(256) void k_transpose(const float* __restrict__ src,
                                                   float* __restrict__ dst,
                                                   int K, int N)
{
    __shared__ float s[32][33];
    const size_t eo = (size_t)blockIdx.z * (size_t)K * N;
    const int n0 = blockIdx.x * 32, k0 = blockIdx.y * 32;
    const int tid = threadIdx.x;

    const int kr = tid >> 3, nq = (tid & 7) * 4;
    float4 v = *(const float4*)(src + eo + (size_t)(k0 + kr) * N + n0 + nq);
    s[kr][nq + 0] = tf32r(v.x);
    s[kr][nq + 1] = tf32r(v.y);
    s[kr][nq + 2] = tf32r(v.z);
    s[kr][nq + 3] = tf32r(v.w);
    __syncthreads();

    const int nr = tid >> 3, kq = (tid & 7) * 4;
    float4 w;
    w.x = s[kq + 0][nr]; w.y = s[kq + 1][nr];
    w.z = s[kq + 2][nr]; w.w = s[kq + 3][nr];
    *(float4*)(dst + eo + (size_t)(n0 + nr) * K + k0 + kq) = w;
}

// ---------------- mma.sync tf32 grouped GEMM, both operands ldmatrix ---------
// Block 128x128, BK=32, 3-stage cp.async, 8 warps (2m x 4n), warp tile 64x32.
// A: [rows][K] k-major (gathered via rowmap for G1, direct for G2), pre-tf32.
// B: W^T [N][K] k-major, pre-tf32.
// IS_G2 == 0: g_H[slot] = relu_tf32(A @ W1t^T + b1[e])   (K=1024, N=4096)
// IS_G2 == 1: g_O[slot] = A @ W2t^T                       (K=4096, N=1024)
template<int IS_G2>
__global__ __launch_bounds__(256, 2) void k_gemm_mma(
    const float* __restrict__ Aglob,
    const float* __restrict__ Wt,
    const float* __restrict__ bglob)
{
    constexpr int BM = 128, BN = 128, BK = 32, ST = 3;
    constexpr int LDA = BK + 4;               // 36 floats
    constexpr int LDB = BK + 4;               // 36 floats ([n][k] rows)
    constexpr int NLD   = IS_G2 ? DIM : HID;  // bias length
    constexpr int KTOT  = IS_G2 ? HID : DIM;
    constexpr int KCH   = KTOT / BK;
    constexpr int ALDIM = IS_G2 ? HID : DIM;
    constexpr int ABY = BM * LDA;             // floats per A stage
    constexpr int BBY = BN * LDB;             // floats per B stage

    extern __shared__ float sm[];
    float* s_bias = sm;                       // BN
    float* As     = sm + BN;                  // ST * ABY
    float* Bs     = As + ST * ABY;            // ST * BBY

    const int e    = blockIdx.z;
    const int base = g_offsets[e];
    const int cnt  = g_offsets[e + 1] - base;
    const int m0   = blockIdx.x * BM;
    if (m0 >= cnt) return;
    const int n0   = blockIdx.y * BN;

    const int tid  = threadIdx.x;
    const int lane = tid & 31, wid = tid >> 5;
    const int wm = wid & 1, wn = wid >> 1;    // 2 m-warps x 4 n-warps
    const int g = lane >> 2, tg = lane & 3;

    const float* We = Wt + (size_t)e * (size_t)KTOT * (IS_G2 ? DIM : HID);

    if (!IS_G2 && tid < BN) s_bias[tid] = bglob[(size_t)e * NLD + n0 + tid];

    // per-thread cp.async slots: A
    const float* asrc[4];
    uint32_t     adst[4];
    #pragma unroll
    for (int j = 0; j < 4; j++) {
        int idx = tid + 256 * j;              // 0..1023
        int r = idx >> 3, kq = idx & 7;
        int slot = base + m0 + r;
        if (slot > MAXROWS - 1) slot = MAXROWS - 1;
        if (IS_G2) asrc[j] = Aglob + (size_t)slot * ALDIM + kq * 4;
        else       asrc[j] = Aglob + (size_t)g_rowmap[slot] * ALDIM + kq * 4;
        adst[j] = smem_u32(As + r * LDA + kq * 4);
    }
    // per-thread cp.async slots: B (W^T rows, k-contiguous)
    const float* bsrc[4];
    uint32_t     bdst[4];
    #pragma unroll
    for (int j = 0; j < 4; j++) {
        int idx = tid + 256 * j;
        int r = idx >> 3, kq = idx & 7;       // r = n-row 0..127
        bsrc[j] = We + (size_t)(n0 + r) * KTOT + kq * 4;
        bdst[j] = smem_u32(Bs + r * LDB + kq * 4);
    }

    // ldmatrix A base addresses (mi = 0..3): regs = {m,k0},{m+8,k0},{m,k4},{m+8,k4}
    uint32_t amat[4];
    {
        int sector = lane >> 3, rowin = lane & 7;
        #pragma unroll
        for (int mi = 0; mi < 4; mi++) {
            int rloc = wm * 64 + mi * 16 + (sector & 1) * 8 + rowin;
            int colb = (sector >> 1) * 4;
            amat[mi] = smem_u32(As + rloc * LDA + colb);
        }
    }
    // ldmatrix B base addresses (ni2 = 0..1, each n16): regs =
    // {n,k0},{n,k4},{n+8,k0},{n+8,k4}  (sector&1 -> k, sector>>1 -> n+8)
    uint32_t bmat[2];
    {
        int sector = lane >> 3, rowin = lane & 7;
        #pragma unroll
        for (int ni2 = 0; ni2 < 2; ni2++) {
            int nrow = wn * 32 + ni2 * 16 + (sector >> 1) * 8 + rowin;
            int kcol = (sector & 1) * 4;
            bmat[ni2] = smem_u32(Bs + nrow * LDB + kcol);
        }
    }

    float acc[4][4][4] = {};

    // prologue: prefetch chunks 0 and 1
    #pragma unroll
    for (int pc = 0; pc < ST - 1; pc++) {
        const uint32_t soa = (uint32_t)(pc * ABY * 4);
        const uint32_t sob = (uint32_t)(pc * BBY * 4);
        const int k0 = pc * BK;
        #pragma unroll
        for (int j = 0; j < 4; j++) CP16(adst[j] + soa, asrc[j] + k0);
        #pragma unroll
        for (int j = 0; j < 4; j++) CP16(bdst[j] + sob, bsrc[j] + k0);
        CP_COMMIT();
    }

    for (int c = 0; c < KCH; c++) {
        CP_WAIT1();          // chunk c resident
        __syncthreads();

        const int wb = (c + ST - 1) % ST;
        if (c + ST - 1 < KCH) {
            const uint32_t soa = (uint32_t)(wb * ABY * 4);
            const uint32_t sob = (uint32_t)(wb * BBY * 4);
            const int k0 = (c + ST - 1) * BK;
            #pragma unroll
            for (int j = 0; j < 4; j++) CP16(adst[j] + soa, asrc[j] + k0);
            #pragma unroll
            for (int j = 0; j < 4; j++) CP16(bdst[j] + sob, bsrc[j] + k0);
        }
        CP_COMMIT();

        const int buf = c % ST;
        const uint32_t aoff = (uint32_t)(buf * ABY * 4);
        const uint32_t boff = (uint32_t)(buf * BBY * 4);

        #pragma unroll
        for (int ks = 0; ks < 4; ks++) {
            uint32_t au[4][4], br[2][4];
            #pragma unroll
            for (int mi = 0; mi < 4; mi++)
                LDSM_X4(au[mi], amat[mi] + aoff + (uint32_t)(ks * 32));
            #pragma unroll
            for (int ni2 = 0; ni2 < 2; ni2++)
                LDSM_X4(br[ni2], bmat[ni2] + boff + (uint32_t)(ks * 32));
            #pragma unroll
            for (int mi = 0; mi < 4; mi++)
                #pragma unroll
                for (int ni = 0; ni < 4; ni++)
                    MMA_TF32(acc[mi][ni], au[mi], &br[ni >> 1][(ni & 1) * 2]);
        }
    }
    CP_WAITALL();

    // ---------------- epilogue ----------------
    #pragma unroll
    for (int mi = 0; mi < 4; mi++) {
        #pragma unroll
        for (int half = 0; half < 2; half++) {
            const int rl = wm * 64 + mi * 16 + half * 8 + g;
            if ((m0 + rl) >= cnt) continue;
            const int slot = base + m0 + rl;
            if (IS_G2) {
                float* orow = g_O + (size_t)slot * DIM + n0;
                #pragma unroll
                for (int ni = 0; ni < 4; ni++) {
                    const int cl = wn * 32 + ni * 8 + tg * 2;
                    float2 v;
                    v.x = acc[mi][ni][half * 2 + 0];
                    v.y = acc[mi][ni][half * 2 + 1];
                    *(float2*)(orow + cl) = v;
                }
            } else {
                float* hrow = g_H + (size_t)slot * HID + n0;
                #pragma unroll
                for (int ni = 0; ni < 4; ni++) {
                    const int cl = wn * 32 + ni * 8 + tg * 2;
                    float2 v;
                    v.x = tf32r(fmaxf(acc[mi][ni][half * 2 + 0] + s_bias[cl], 0.f));
                    v.y = tf32r(fmaxf(acc[mi][ni][half * 2 + 1] + s_bias[cl + 1], 0.f));
                    *(float2*)(hrow + cl) = v;
                }
            }
        }
    }
}

// ---------------- K5: combine out[t] = sum_k w_k * (o_k + b2[e_k]) ----------
__global__ void k_combine(const float* __restrict__ b2, float* __restrict__ out)
{
    int t = blockIdx.x;
    int d = threadIdx.x * 4;
    int e0 = g_tok_e[t * 2], e1 = g_tok_e[t * 2 + 1];
    float w0 = g_tok_w[t * 2], w1 = g_tok_w[t * 2 + 1];
    int s0 = g_tok_slot[t * 2], s1 = g_tok_slot[t * 2 + 1];

    float4 o0 = *(const float4*)(g_O + (size_t)s0 * DIM + d);
    float4 o1 = *(const float4*)(g_O + (size_t)s1 * DIM + d);
    float4 c0 = *(const float4*)(b2 + (size_t)e0 * DIM + d);
    float4 c1 = *(const float4*)(b2 + (size_t)e1 * DIM + d);

    float4 r;
    r.x = w0 * (o0.x + c0.x) + w1 * (o1.x + c1.x);
    r.y = w0 * (o0.y + c0.y) + w1 * (o1.y + c1.y);
    r.z = w0 * (o0.z + c0.z) + w1 * (o1.z + c1.z);
    r.w = w0 * (o0.w + c0.w) + w1 * (o1.w + c1.w);
    *(float4*)(out + (size_t)t * DIM + d) = r;
}

// ---------------- launch -----------------------------------------------------
extern "C" void kernel_launch(void* const* d_in, const int* in_sizes, int n_in,
                              void* d_out, int out_size)
{
    const float* u    = (const float*)d_in[0];
    const float* cent = (const float*)d_in[1];
    const float* bias = (const float*)d_in[2];
    const float* W1   = (const float*)d_in[3];
    const float* b1   = (const float*)d_in[4];
    const float* W2   = (const float*)d_in[5];
    const float* b2   = (const float*)d_in[6];
    float* out = (float*)d_out;

    float* maxvio_ptr;
    if (out_size > T_TOK * DIM) {
        maxvio_ptr = out + (size_t)T_TOK * DIM;
    } else {
        cudaGetSymbolAddress((void**)&maxvio_ptr, g_dummy);
    }
    float* uruf;  cudaGetSymbolAddress((void**)&uruf, g_U);
    float* hbuf;  cudaGetSymbolAddress((void**)&hbuf, g_H);
    float* w1t;   cudaGetSymbolAddress((void**)&w1t,  g_W1t);
    float* w2t;   cudaGetSymbolAddress((void**)&w2t,  g_W2t);

    // smem: 128 + 3*128*36*2 floats = 128 + 27648 = 27776 floats = 111104 B
    const int SMEM = 27776 * 4;
    cudaFuncSetAttribute(k_gemm_mma<0>, cudaFuncAttributeMaxDynamicSharedMemorySize, SMEM);
    cudaFuncSetAttribute(k_gemm_mma<1>, cudaFuncAttributeMaxDynamicSharedMemorySize, SMEM);

    k_prep<<<(T_TOK * DIM / 4 + 255) / 256, 256>>>(u);                    // idx 0
    k_router<<<T_TOK, 256>>>(u, cent, bias);                              // idx 1
    k_offscatter<<<1, 1024>>>(maxvio_ptr);                                // idx 2
    k_transpose<<<dim3(HID / 32, DIM / 32, NEXP), 256>>>(W1, w1t, DIM, HID); // idx 3
    k_transpose<<<dim3(DIM / 32, HID / 32, NEXP), 256>>>(W2, w2t, HID, DIM); // idx 4
    k_gemm_mma<0><<<dim3(16, HID / 128, NEXP), 256, SMEM>>>(uruf, w1t, b1);  // idx 5
    k_gemm_mma<1><<<dim3(16, DIM / 128, NEXP), 256, SMEM>>>(hbuf, w2t, b2);  // idx 6
    k_combine<<<T_TOK, 256>>>(b2, out);                                   // idx 7
}

// round 7
// speedup vs baseline: 1.0057x; 1.0057x over previous
#include <cuda_runtime.h>
#include <cstdint>
#include <math.h>

#define T_TOK   2048
#define DIM     1024
#define NEXP    8
#define HID     4096
#define TOPK    2
#define MAXROWS (T_TOK * TOPK)   // 4096

// ---------------- scratch (__device__ globals) -------------------------------
__device__ float g_H[(size_t)MAXROWS * HID];        // 64 MB hidden acts (tf32)
__device__ float g_U[(size_t)T_TOK * DIM];          // 8 MB tf32-rounded inputs
__device__ float g_O[(size_t)MAXROWS * DIM];        // 16 MB expert outputs
__device__ float g_W1t[(size_t)NEXP * HID * DIM];   // 134 MB W1^T (tf32) [e][n][k]
__device__ float g_W2t[(size_t)NEXP * DIM * HID];   // 134 MB W2^T (tf32) [e][n][k]
__device__ int   g_rowmap[MAXROWS];                 // slot -> token
__device__ int   g_counts[NEXP];
__device__ int   g_offsets[NEXP + 1];
__device__ int   g_tok_e[T_TOK * TOPK];
__device__ float g_tok_w[T_TOK * TOPK];
__device__ int   g_tok_slot[T_TOK * TOPK];
__device__ float g_dummy[1];

// ---------------- helpers ----------------------------------------------------
__device__ __forceinline__ uint32_t smem_u32(const void* p) {
    uint32_t a;
    asm("{ .reg .u64 t; cvta.to.shared.u64 t, %1; cvt.u32.u64 %0, t; }"
        : "=r"(a) : "l"(p));
    return a;
}
__device__ __forceinline__ float tf32r(float x) {
    float r;
    asm("cvt.rna.tf32.f32 %0, %1;" : "=f"(r) : "f"(x));
    return r;
}

#define CP16(dst, src) \
    asm volatile("cp.async.cg.shared.global [%0], [%1], 16;" :: "r"(dst), "l"(src))
#define CP_COMMIT()  asm volatile("cp.async.commit_group;" ::: "memory")
#define CP_WAIT1()   asm volatile("cp.async.wait_group 1;" ::: "memory")
#define CP_WAITALL() asm volatile("cp.async.wait_all;" ::: "memory")

#define LDSM_X4(r, addr) \
    asm volatile("ldmatrix.sync.aligned.m8n8.x4.shared.b16 {%0,%1,%2,%3}, [%4];" \
        : "=r"((r)[0]), "=r"((r)[1]), "=r"((r)[2]), "=r"((r)[3]) : "r"(addr))

#define MMA_TF32(d, a, b) \
    asm volatile("mma.sync.aligned.m16n8k8.row.col.f32.tf32.tf32.f32 " \
        "{%0,%1,%2,%3}, {%4,%5,%6,%7}, {%8,%9}, {%0,%1,%2,%3};" \
        : "+f"((d)[0]), "+f"((d)[1]), "+f"((d)[2]), "+f"((d)[3]) \
        : "r"((a)[0]), "r"((a)[1]), "r"((a)[2]), "r"((a)[3]), \
          "r"((b)[0]), "r"((b)[1]))

// ---------------- K0: round u -> g_U, reset counters -------------------------
__global__ void k_prep(const float* __restrict__ u)
{
    size_t i = ((size_t)blockIdx.x * blockDim.x + threadIdx.x) * 4;
    if (i < (size_t)T_TOK * DIM) {
        float4 v = *(const float4*)(u + i);
        v.x = tf32r(v.x); v.y = tf32r(v.y); v.z = tf32r(v.z); v.w = tf32r(v.w);
        *(float4*)(g_U + i) = v;
    }
    if (blockIdx.x == 0 && threadIdx.x < NEXP) g_counts[threadIdx.x] = 0;
}

// ---------------- K1: router -------------------------------------------------
__global__ void k_router(const float* __restrict__ u,
                         const float* __restrict__ cent,
                         const float* __restrict__ bias)
{
    int t    = blockIdx.x;
    int warp = threadIdx.x >> 5;
    int lane = threadIdx.x & 31;

    const float* ur = u + (size_t)t * DIM;
    const float* cr = cent + (size_t)warp * DIM;

    float s = 0.f;
    #pragma unroll 8
    for (int i = lane; i < DIM; i += 32) s += ur[i] * cr[i];
    #pragma unroll
    for (int o = 16; o; o >>= 1) s += __shfl_xor_sync(0xffffffffu, s, o);

    __shared__ float sc[NEXP];
    if (lane == 0) sc[warp] = s + bias[warp];
    __syncthreads();

    if (threadIdx.x == 0) {
        float m = sc[0];
        #pragma unroll
        for (int e = 1; e < NEXP; e++) m = fmaxf(m, sc[e]);
        float p[NEXP];
        float den = 0.f;
        #pragma unroll
        for (int e = 0; e < NEXP; e++) { p[e] = __expf(sc[e] - m); den += p[e]; }

        int e0 = 0;
        #pragma unroll
        for (int e = 1; e < NEXP; e++) if (p[e] > p[e0]) e0 = e;
        int e1 = (e0 == 0) ? 1 : 0;
        #pragma unroll
        for (int e = 0; e < NEXP; e++) if (e != e0 && p[e] > p[e1]) e1 = e;

        float inv = 1.f / den;
        g_tok_e[t * 2 + 0] = e0;  g_tok_w[t * 2 + 0] = p[e0] * inv;
        g_tok_e[t * 2 + 1] = e1;  g_tok_w[t * 2 + 1] = p[e1] * inv;
        atomicAdd(&g_counts[e0], 1);
        atomicAdd(&g_counts[e1], 1);
    }
}

// ---------------- K2: fused offsets + maxvio + scatter (single block) --------
__global__ void k_offscatter(float* __restrict__ maxvio_out)
{
    __shared__ int s_off[NEXP];
    __shared__ int s_cur[NEXP];
    int tid = threadIdx.x;
    if (tid < NEXP) s_cur[tid] = 0;
    if (tid == 0) {
        int off = 0, mx = 0;
        #pragma unroll
        for (int e = 0; e < NEXP; e++) {
            s_off[e] = off;
            g_offsets[e] = off;
            int c = g_counts[e];
            off += c;
            if (c > mx) mx = c;
        }
        g_offsets[NEXP] = off;
        const float perfect = (float)(TOPK * T_TOK) / (float)NEXP;
        *maxvio_out = ((float)mx - perfect) / perfect;
    }
    __syncthreads();
    for (int t = tid; t < T_TOK; t += blockDim.x) {
        #pragma unroll
        for (int k = 0; k < TOPK; k++) {
            int e = g_tok_e[t * 2 + k];
            int slot = s_off[e] + atomicAdd(&s_cur[e], 1);
            g_rowmap[slot] = t;
            g_tok_slot[t * 2 + k] = slot;
        }
    }
}

// ---------------- K3: tiled transpose + tf32 round: [e][K][N] -> [e][N][K] ---
__global__ __launch_bounds__(256) void k_transpose(const float* __restrict__ src,
                                                   float* __restrict__ dst,
                                                   int K, int N)
{
    __shared__ float s[32][33];
    const size_t eo = (size_t)blockIdx.z * (size_t)K * N;
    const int n0 = blockIdx.x * 32, k0 = blockIdx.y * 32;
    const int tid = threadIdx.x;

    const int kr = tid >> 3, nq = (tid & 7) * 4;
    float4 v = *(const float4*)(src + eo + (size_t)(k0 + kr) * N + n0 + nq);
    s[kr][nq + 0] = tf32r(v.x);
    s[kr][nq + 1] = tf32r(v.y);
    s[kr][nq + 2] = tf32r(v.z);
    s[kr][nq + 3] = tf32r(v.w);
    __syncthreads();

    const int nr = tid >> 3, kq = (tid & 7) * 4;
    float4 w;
    w.x = s[kq + 0][nr]; w.y = s[kq + 1][nr];
    w.z = s[kq + 2][nr]; w.w = s[kq + 3][nr];
    *(float4*)(dst + eo + (size_t)(n0 + nr) * K + k0 + kq) = w;
}

// ---------------- mma.sync tf32 grouped GEMM, both operands ldmatrix ---------
// Block 128x128, BK=32, 3-stage cp.async, 8 warps (2m x 4n), warp tile 64x32.
// IS_G2 == 0: g_H[slot] = relu_tf32(A @ W1t^T + b1[e])   (K=1024, N=4096)
// IS_G2 == 1: g_O[slot] = A @ W2t^T                       (K=4096, N=1024)
template<int IS_G2>
__global__ __launch_bounds__(256, 2) void k_gemm_mma(
    const float* __restrict__ Aglob,
    const float* __restrict__ Wt,
    const float* __restrict__ bglob)
{
    constexpr int BM = 128, BN = 128, BK = 32, ST = 3;
    constexpr int LDA = BK + 4;               // 36 floats
    constexpr int LDB = BK + 4;               // 36 floats ([n][k] rows)
    constexpr int NLD   = IS_G2 ? DIM : HID;  // bias length
    constexpr int KTOT  = IS_G2 ? HID : DIM;
    constexpr int KCH   = KTOT / BK;
    constexpr int ALDIM = IS_G2 ? HID : DIM;
    constexpr int ABY = BM * LDA;             // floats per A stage
    constexpr int BBY = BN * LDB;             // floats per B stage

    extern __shared__ float sm[];
    float* s_bias = sm;                       // BN
    float* As     = sm + BN;                  // ST * ABY
    float* Bs     = As + ST * ABY;            // ST * BBY

    const int e    = blockIdx.z;
    const int base = g_offsets[e];
    const int cnt  = g_offsets[e + 1] - base;
    const int m0   = blockIdx.x * BM;
    if (m0 >= cnt) return;
    const int n0   = blockIdx.y * BN;

    const int tid  = threadIdx.x;
    const int lane = tid & 31, wid = tid >> 5;
    const int wm = wid & 1, wn = wid >> 1;    // 2 m-warps x 4 n-warps
    const int g = lane >> 2, tg = lane & 3;

    const float* We = Wt + (size_t)e * (size_t)KTOT * (IS_G2 ? DIM : HID);

    if (!IS_G2 && tid < BN) s_bias[tid] = bglob[(size_t)e * NLD + n0 + tid];

    // per-thread cp.async slots: A
    const float* asrc[4];
    uint32_t     adst[4];
    #pragma unroll
    for (int j = 0; j < 4; j++) {
        int idx = tid + 256 * j;              // 0..1023
        int r = idx >> 3, kq = idx & 7;
        int slot = base + m0 + r;
        if (slot > MAXROWS - 1) slot = MAXROWS - 1;
        if (IS_G2) asrc[j] = Aglob + (size_t)slot * ALDIM + kq * 4;
        else       asrc[j] = Aglob + (size_t)g_rowmap[slot] * ALDIM + kq * 4;
        adst[j] = smem_u32(As + r * LDA + kq * 4);
    }
    // per-thread cp.async slots: B (W^T rows, k-contiguous)
    const float* bsrc[4];
    uint32_t     bdst[4];
    #pragma unroll
    for (int j = 0; j < 4; j++) {
        int idx = tid + 256 * j;
        int r = idx >> 3, kq = idx & 7;       // r = n-row 0..127
        bsrc[j] = We + (size_t)(n0 + r) * KTOT + kq * 4;
        bdst[j] = smem_u32(Bs + r * LDB + kq * 4);
    }

    // ldmatrix A base addresses (mi = 0..3)
    uint32_t amat[4];
    {
        int sector = lane >> 3, rowin = lane & 7;
        #pragma unroll
        for (int mi = 0; mi < 4; mi++) {
            int rloc = wm * 64 + mi * 16 + (sector & 1) * 8 + rowin;
            int colb = (sector >> 1) * 4;
            amat[mi] = smem_u32(As + rloc * LDA + colb);
        }
    }
    // ldmatrix B base addresses (ni2 = 0..1, each n16)
    uint32_t bmat[2];
    {
        int sector = lane >> 3, rowin = lane & 7;
        #pragma unroll
        for (int ni2 = 0; ni2 < 2; ni2++) {
            int nrow = wn * 32 + ni2 * 16 + (sector >> 1) * 8 + rowin;
            int kcol = (sector & 1) * 4;
            bmat[ni2] = smem_u32(Bs + nrow * LDB + kcol);
        }
    }

    float acc[4][4][4] = {};

    // prologue: prefetch chunks 0 and 1
    #pragma unroll
    for (int pc = 0; pc < ST - 1; pc++) {
        const uint32_t soa = (uint32_t)(pc * ABY * 4);
        const uint32_t sob = (uint32_t)(pc * BBY * 4);
        const int k0 = pc * BK;
        #pragma unroll
        for (int j = 0; j < 4; j++) CP16(adst[j] + soa, asrc[j] + k0);
        #pragma unroll
        for (int j = 0; j < 4; j++) CP16(bdst[j] + sob, bsrc[j] + k0);
        CP_COMMIT();
    }

    for (int c = 0; c < KCH; c++) {
        CP_WAIT1();          // chunk c resident
        __syncthreads();

        const int wb = (c + ST - 1) % ST;
        if (c + ST - 1 < KCH) {
            const uint32_t soa = (uint32_t)(wb * ABY * 4);
            const uint32_t sob = (uint32_t)(wb * BBY * 4);
            const int k0 = (c + ST - 1) * BK;
            #pragma unroll
            for (int j = 0; j < 4; j++) CP16(adst[j] + soa, asrc[j] + k0);
            #pragma unroll
            for (int j = 0; j < 4; j++) CP16(bdst[j] + sob, bsrc[j] + k0);
        }
        CP_COMMIT();

        const int buf = c % ST;
        const uint32_t aoff = (uint32_t)(buf * ABY * 4);
        const uint32_t boff = (uint32_t)(buf * BBY * 4);

        #pragma unroll
        for (int ks = 0; ks < 4; ks++) {
            uint32_t au[4][4], br[2][4];
            #pragma unroll
            for (int mi = 0; mi < 4; mi++)
                LDSM_X4(au[mi], amat[mi] + aoff + (uint32_t)(ks * 32));
            #pragma unroll
            for (int ni2 = 0; ni2 < 2; ni2++)
                LDSM_X4(br[ni2], bmat[ni2] + boff + (uint32_t)(ks * 32));
            #pragma unroll
            for (int mi = 0; mi < 4; mi++)
                #pragma unroll
                for (int ni = 0; ni < 4; ni++)
                    MMA_TF32(acc[mi][ni], au[mi], &br[ni >> 1][(ni & 1) * 2]);
        }
    }
    CP_WAITALL();

    // ---------------- epilogue ----------------
    #pragma unroll
    for (int mi = 0; mi < 4; mi++) {
        #pragma unroll
        for (int half = 0; half < 2; half++) {
            const int rl = wm * 64 + mi * 16 + half * 8 + g;
            if ((m0 + rl) >= cnt) continue;
            const int slot = base + m0 + rl;
            if (IS_G2) {
                float* orow = g_O + (size_t)slot * DIM + n0;
                #pragma unroll
                for (int ni = 0; ni < 4; ni++) {
                    const int cl = wn * 32 + ni * 8 + tg * 2;
                    float2 v;
                    v.x = acc[mi][ni][half * 2 + 0];
                    v.y = acc[mi][ni][half * 2 + 1];
                    *(float2*)(orow + cl) = v;
                }
            } else {
                float* hrow = g_H + (size_t)slot * HID + n0;
                #pragma unroll
                for (int ni = 0; ni < 4; ni++) {
                    const int cl = wn * 32 + ni * 8 + tg * 2;
                    float2 v;
                    v.x = tf32r(fmaxf(acc[mi][ni][half * 2 + 0] + s_bias[cl], 0.f));
                    v.y = tf32r(fmaxf(acc[mi][ni][half * 2 + 1] + s_bias[cl + 1], 0.f));
                    *(float2*)(hrow + cl) = v;
                }
            }
        }
    }
}

// ---------------- K5: combine out[t] = sum_k w_k * (o_k + b2[e_k]) ----------
__global__ void k_combine(const float* __restrict__ b2, float* __restrict__ out)
{
    int t = blockIdx.x;
    int d = threadIdx.x * 4;
    int e0 = g_tok_e[t * 2], e1 = g_tok_e[t * 2 + 1];
    float w0 = g_tok_w[t * 2], w1 = g_tok_w[t * 2 + 1];
    int s0 = g_tok_slot[t * 2], s1 = g_tok_slot[t * 2 + 1];

    float4 o0 = *(const float4*)(g_O + (size_t)s0 * DIM + d);
    float4 o1 = *(const float4*)(g_O + (size_t)s1 * DIM + d);
    float4 c0 = *(const float4*)(b2 + (size_t)e0 * DIM + d);
    float4 c1 = *(const float4*)(b2 + (size_t)e1 * DIM + d);

    float4 r;
    r.x = w0 * (o0.x + c0.x) + w1 * (o1.x + c1.x);
    r.y = w0 * (o0.y + c0.y) + w1 * (o1.y + c1.y);
    r.z = w0 * (o0.z + c0.z) + w1 * (o1.z + c1.z);
    r.w = w0 * (o0.w + c0.w) + w1 * (o1.w + c1.w);
    *(float4*)(out + (size_t)t * DIM + d) = r;
}

// ---------------- launch (stream-forked: transposes overlap GEMM1) ----------
extern "C" void kernel_launch(void* const* d_in, const int* in_sizes, int n_in,
                              void* d_out, int out_size)
{
    const float* u    = (const float*)d_in[0];
    const float* cent = (const float*)d_in[1];
    const float* bias = (const float*)d_in[2];
    const float* W1   = (const float*)d_in[3];
    const float* b1   = (const float*)d_in[4];
    const float* W2   = (const float*)d_in[5];
    const float* b2   = (const float*)d_in[6];
    float* out = (float*)d_out;

    float* maxvio_ptr;
    if (out_size > T_TOK * DIM) {
        maxvio_ptr = out + (size_t)T_TOK * DIM;
    } else {
        cudaGetSymbolAddress((void**)&maxvio_ptr, g_dummy);
    }
    float* uruf;  cudaGetSymbolAddress((void**)&uruf, g_U);
    float* hbuf;  cudaGetSymbolAddress((void**)&hbuf, g_H);
    float* w1t;   cudaGetSymbolAddress((void**)&w1t,  g_W1t);
    float* w2t;   cudaGetSymbolAddress((void**)&w2t,  g_W2t);

    // one-time host resources (same launch pattern every call)
    static cudaStream_t s_aux = nullptr;
    static cudaEvent_t  ev_fork = nullptr, ev_w1 = nullptr, ev_w2 = nullptr;
    if (s_aux == nullptr) {
        cudaStreamCreateWithFlags(&s_aux, cudaStreamNonBlocking);
        cudaEventCreateWithFlags(&ev_fork, cudaEventDisableTiming);
        cudaEventCreateWithFlags(&ev_w1,   cudaEventDisableTiming);
        cudaEventCreateWithFlags(&ev_w2,   cudaEventDisableTiming);
    }

    // smem: 128 + 3*128*36*2 floats = 27776 floats = 111104 B
    const int SMEM = 27776 * 4;
    cudaFuncSetAttribute(k_gemm_mma<0>, cudaFuncAttributeMaxDynamicSharedMemorySize, SMEM);
    cudaFuncSetAttribute(k_gemm_mma<1>, cudaFuncAttributeMaxDynamicSharedMemorySize, SMEM);

    // fork: aux stream transposes W1 then W2 while main stream routes
    cudaEventRecord(ev_fork, 0);
    cudaStreamWaitEvent(s_aux, ev_fork, 0);
    k_transpose<<<dim3(HID / 32, DIM / 32, NEXP), 256, 0, s_aux>>>(W1, w1t, DIM, HID);
    cudaEventRecord(ev_w1, s_aux);
    k_transpose<<<dim3(DIM / 32, HID / 32, NEXP), 256, 0, s_aux>>>(W2, w2t, HID, DIM);
    cudaEventRecord(ev_w2, s_aux);

    // main stream: routing pipeline
    k_prep<<<(T_TOK * DIM / 4 + 255) / 256, 256>>>(u);
    k_router<<<T_TOK, 256>>>(u, cent, bias);
    k_offscatter<<<1, 1024>>>(maxvio_ptr);

    cudaStreamWaitEvent(0, ev_w1, 0);       // join W1^T
    k_gemm_mma<0><<<dim3(16, HID / 128, NEXP), 256, SMEM>>>(uruf, w1t, b1);
    cudaStreamWaitEvent(0, ev_w2, 0);       // join W2^T (done under gemm1)
    k_gemm_mma<1><<<dim3(16, DIM / 128, NEXP), 256, SMEM>>>(hbuf, w2t, b2);
    k_combine<<<T_TOK, 256>>>(b2, out);
}